// round 15
// baseline (speedup 1.0000x reference)
#include <cuda_runtime.h>
#include <cuda_bf16.h>
#include <cstdint>

// ---------------------------------------------------------------------------
// Problem constants
// ---------------------------------------------------------------------------
#define BB 64
#define SS 8192
#define DD 128
#define UU 128
#define FF 16
#define CLIP_C 10.0f
#define BIG_NUMBER 1e9f
#define TS 128
#define NTILES 4096          // (SS/TS) * BB ; tile t: b = t>>6, s0 = (t&63)*TS
#define GRID_MAIN 152        // GB300 SM count

// Scratch (device globals; no allocation allowed)
__device__ float          g_qb[BB * UU];
__device__ __nv_bfloat16  g_W2T_hi[UU * DD];
__device__ __nv_bfloat16  g_W2T_lo[UU * DD];
__device__ float          g_psum[NTILES];    // per-tile sum of exp(logit-10)
__device__ float          g_pmaxv[NTILES];   // per-tile max logit
__device__ int            g_pmaxi[NTILES];   // per-tile argmax (first occurrence)

// ---------------------------------------------------------------------------
// Helpers (baseline PTX only)
// ---------------------------------------------------------------------------
__device__ __forceinline__ uint32_t smem_u32(const void* p) {
    uint32_t a;
    asm("{ .reg .u64 t; cvta.to.shared.u64 t, %1; cvt.u32.u64 %0, t; }"
        : "=r"(a) : "l"(p));
    return a;
}

#define LDMX4(r0, r1, r2, r3, addr) \
    asm volatile("ldmatrix.sync.aligned.m8n8.x4.shared.b16 {%0,%1,%2,%3}, [%4];" \
                 : "=r"(r0), "=r"(r1), "=r"(r2), "=r"(r3) : "r"(addr))

#define MMA16816(c0, c1, c2, c3, a0, a1, a2, a3, b0, b1) \
    asm volatile("mma.sync.aligned.m16n8k16.row.col.f32.bf16.bf16.f32 " \
                 "{%0,%1,%2,%3}, {%4,%5,%6,%7}, {%8,%9}, {%0,%1,%2,%3};" \
                 : "+f"(c0), "+f"(c1), "+f"(c2), "+f"(c3) \
                 : "r"(a0), "r"(a1), "r"(a2), "r"(a3), "r"(b0), "r"(b1))

__device__ __forceinline__ float fast_tanh(float x) {
    float e, r;
    asm("ex2.approx.f32 %0, %1;" : "=f"(e) : "f"(x * 2.885390081777927f));
    asm("rcp.approx.f32 %0, %1;" : "=f"(r) : "f"(e + 1.0f));
    return fmaf(-2.0f, r, 1.0f);
}

__device__ __forceinline__ float fast_exp(float x) {
    float e;
    asm("ex2.approx.f32 %0, %1;" : "=f"(e) : "f"(x * 1.4426950408889634f));
    return e;
}

// convert one fp32 float4 -> bf16 hi/lo packed pairs, store to A buffers
__device__ __forceinline__ void cvt_store(unsigned char* base_hi,
                                          unsigned char* base_lo,
                                          uint32_t off, float4 x) {
    __nv_bfloat16 h0 = __float2bfloat16(x.x), h1 = __float2bfloat16(x.y);
    __nv_bfloat16 h2 = __float2bfloat16(x.z), h3 = __float2bfloat16(x.w);
    __nv_bfloat162 hp0 = __halves2bfloat162(h0, h1);
    __nv_bfloat162 hp1 = __halves2bfloat162(h2, h3);
    __nv_bfloat162 lp0 = __halves2bfloat162(
        __float2bfloat16(x.x - __bfloat162float(h0)),
        __float2bfloat16(x.y - __bfloat162float(h1)));
    __nv_bfloat162 lp1 = __halves2bfloat162(
        __float2bfloat16(x.z - __bfloat162float(h2)),
        __float2bfloat16(x.w - __bfloat162float(h3)));
    *(uint2*)(base_hi + off) = make_uint2(*(uint32_t*)&hp0, *(uint32_t*)&hp1);
    *(uint2*)(base_lo + off) = make_uint2(*(uint32_t*)&lp0, *(uint32_t*)&lp1);
}

// ---------------------------------------------------------------------------
// Prep: qb (blocks 0..63, W1 cached in smem) + W2^T bf16 split (64..79)
// ---------------------------------------------------------------------------
extern __shared__ float prep_sm[];

__global__ void prep_kernel(const float* __restrict__ dec,
                            const float* __restrict__ W1w,
                            const float* __restrict__ W1b,
                            const float* __restrict__ W2b,
                            const float* __restrict__ W2w) {
    int blk = blockIdx.x;
    int tid = threadIdx.x;
    if (blk < BB) {
        __shared__ float dsh[DD];
        if (tid < DD) dsh[tid] = dec[blk * DD + tid];
        for (int i = tid; i < (DD * UU) / 4; i += 256)
            ((float4*)prep_sm)[i] = ((const float4*)W1w)[i];
        __syncthreads();
        if (tid < UU) {
            float acc = 0.f;
#pragma unroll 8
            for (int d = 0; d < DD; d++) acc += dsh[d] * prep_sm[d * UU + tid];
            g_qb[blk * UU + tid] = acc + W1b[tid] + W2b[tid];
        }
    } else if (tid < 128) {
        int j = blk - BB;
        int u = tid;
#pragma unroll
        for (int k = 0; k < 8; k++) {
            int d = j * 8 + k;
            float x = W2w[d * UU + u];
            __nv_bfloat16 h = __float2bfloat16(x);
            float lo = x - __bfloat162float(h);
            g_W2T_hi[u * DD + d] = h;
            g_W2T_lo[u * DD + d] = __float2bfloat16(lo);
        }
    }
}

// ---------------------------------------------------------------------------
// Main: persistent CTAs, static schedule, double-buffered A with interleaved
// LDG+convert in the MMA kk-loop. Epilogue additionally emits per-tile
// softmax partials (sum of exp(l-10), max, first-occurrence argmax).
// ---------------------------------------------------------------------------
#define ROWB 272u
#define SM_W_HI  0u
#define SM_W_LO  (SM_W_HI + 128u * ROWB)     // 34816
#define SM_A0    (SM_W_LO + 128u * ROWB)     // 69632  (hi at +0, lo at +34816)
#define SM_A1    (SM_A0 + 2u * 128u * ROWB)  // 139264
#define SM_AUX   (SM_A1 + 2u * 128u * ROWB)  // 208896
#define SM_Q0    (SM_AUX)                    // 128 f32
#define SM_Q1    (SM_AUX + 512u)             // 128 f32
#define SM_V     (SM_AUX + 1024u)            // 128 f32
#define SM_PART  (SM_AUX + 1536u)            // 128*2 f32
#define SM_RED   (SM_AUX + 2560u)            // 8*(f32 sum, f32 max, i32 idx)
#define SM_TOTAL (SM_AUX + 2688u)            // 211584

extern __shared__ unsigned char smx[];

__global__ void __launch_bounds__(256, 1)
main_kernel(const float* __restrict__ enc_out,
            const float* __restrict__ mask,
            const float* __restrict__ Vw,
            const float* __restrict__ Vb,
            float* __restrict__ logits) {
    const int bid = blockIdx.x;
    const int tid = threadIdx.x;
    const int wid = tid >> 5;
    const int lid = tid & 31;
    const int warp_m = wid & 3;
    const int warp_n = wid >> 2;
    const uint32_t sb = smem_u32(smx);

    float* sh_v    = (float*)(smx + SM_V);
    float* sh_part = (float*)(smx + SM_PART);
    float* sh_rs   = (float*)(smx + SM_RED);         // 8 sums
    float* sh_rm   = (float*)(smx + SM_RED + 32u);   // 8 maxes
    int*   sh_ri   = (int*)  (smx + SM_RED + 64u);   // 8 idxs

    const float vb = Vb[0];
    if (tid < UU) sh_v[tid] = Vw[tid];

    // ---- W fill ONCE per CTA ----
    {
        const int row  = tid >> 1;
        const int half = tid & 1;
        const uint4* shi = (const uint4*)((const char*)g_W2T_hi + row * 256 + half * 128);
        const uint4* slo = (const uint4*)((const char*)g_W2T_lo + row * 256 + half * 128);
        uint4* dhi = (uint4*)(smx + SM_W_HI + row * ROWB + half * 128);
        uint4* dlo = (uint4*)(smx + SM_W_LO + row * ROWB + half * 128);
#pragma unroll
        for (int i = 0; i < 8; i++) { dhi[i] = shi[i]; dlo[i] = slo[i]; }
    }

    // ---- initial convert of tile t into A0 (latency exposed once) ----
    int t = bid;
    if (t < NTILES) {
        const int b  = t >> 6;
        const int s0 = (t & 63) * TS;
        const float* src = enc_out + ((size_t)b * SS + s0) * DD;
        unsigned char* bhi = smx + SM_A0;
        unsigned char* blo = smx + SM_A0 + 34816u;
#pragma unroll
        for (int i = 0; i < 16; i++) {
            int r = wid + 8 * i;
            float4 x = *(const float4*)(src + (size_t)r * DD + lid * 4);
            cvt_store(bhi, blo, (uint32_t)r * ROWB + (uint32_t)lid * 8u, x);
        }
        if (tid < UU) ((float*)(smx + SM_Q0))[tid] = g_qb[b * UU + tid];
    }
    __syncthreads();

    // ---- per-lane ldmatrix base offsets (relative) ----
    const uint32_t a_off = (uint32_t)(lid & 15) * ROWB + (uint32_t)((lid >> 4) & 1) * 16u
                           + (uint32_t)(warp_m * 32) * ROWB;
    const uint32_t b_off = ((uint32_t)(lid & 7) + (uint32_t)((lid >> 4) & 1) * 8u) * ROWB
                           + (uint32_t)((lid >> 3) & 1) * 16u
                           + (uint32_t)(warp_n * 64) * ROWB;
    const uint32_t w_hi_base = sb + SM_W_HI + b_off;
    const uint32_t w_lo_base = sb + SM_W_LO + b_off;

    int cur = 0;
    while (t < NTILES) {
        const int b  = t >> 6;
        const int s0 = (t & 63) * TS;
        const int tn = t + GRID_MAIN;
        const bool pf = tn < NTILES;

        const uint32_t a_cur = cur ? SM_A1 : SM_A0;
        const uint32_t a_alt = cur ? SM_A0 : SM_A1;
        const uint32_t a_hi_base = sb + a_cur + a_off;
        const uint32_t a_lo_base = sb + a_cur + 34816u + a_off;
        unsigned char* alt_hi = smx + a_alt;
        unsigned char* alt_lo = smx + a_alt + 34816u;
        float* sh_q  = (float*)(smx + (cur ? SM_Q1 : SM_Q0));
        float* sh_qn = (float*)(smx + (cur ? SM_Q0 : SM_Q1));

        const float* nsrc = nullptr;
        if (pf) {
            const int bn  = tn >> 6;
            const int sn0 = (tn & 63) * TS;
            nsrc = enc_out + ((size_t)bn * SS + sn0) * DD;
            if (tid < UU) sh_qn[tid] = g_qb[bn * UU + tid];
        }

        // ---- fused 3-term MMA mainloop + interleaved next-tile convert ----
        float acc[2][8][4];
#pragma unroll
        for (int mi = 0; mi < 2; mi++)
#pragma unroll
            for (int ni = 0; ni < 8; ni++)
#pragma unroll
                for (int j = 0; j < 4; j++) acc[mi][ni][j] = 0.f;

#pragma unroll 1
        for (int kk = 0; kk < 8; kk++) {
            const uint32_t kb = (uint32_t)kk * 32u;

            float4 nx0, nx1;
            int r0 = wid + 8 * (2 * kk);
            int r1 = wid + 8 * (2 * kk + 1);
            if (pf) {
                nx0 = *(const float4*)(nsrc + (size_t)r0 * DD + lid * 4);
                nx1 = *(const float4*)(nsrc + (size_t)r1 * DD + lid * 4);
            }

            uint32_t ahi[2][4], alo[2][4];
            LDMX4(ahi[0][0], ahi[0][1], ahi[0][2], ahi[0][3], a_hi_base + kb);
            LDMX4(ahi[1][0], ahi[1][1], ahi[1][2], ahi[1][3], a_hi_base + 16u * ROWB + kb);
            LDMX4(alo[0][0], alo[0][1], alo[0][2], alo[0][3], a_lo_base + kb);
            LDMX4(alo[1][0], alo[1][1], alo[1][2], alo[1][3], a_lo_base + 16u * ROWB + kb);
            uint32_t whi[8][2], wlo[8][2];
#pragma unroll
            for (int np = 0; np < 4; np++) {
                LDMX4(whi[2 * np][0], whi[2 * np][1], whi[2 * np + 1][0], whi[2 * np + 1][1],
                      w_hi_base + (uint32_t)(np * 16) * ROWB + kb);
                LDMX4(wlo[2 * np][0], wlo[2 * np][1], wlo[2 * np + 1][0], wlo[2 * np + 1][1],
                      w_lo_base + (uint32_t)(np * 16) * ROWB + kb);
            }
#pragma unroll
            for (int mi = 0; mi < 2; mi++) {
#pragma unroll
                for (int ni = 0; ni < 8; ni++) {
                    MMA16816(acc[mi][ni][0], acc[mi][ni][1], acc[mi][ni][2], acc[mi][ni][3],
                             ahi[mi][0], ahi[mi][1], ahi[mi][2], ahi[mi][3],
                             whi[ni][0], whi[ni][1]);
                    MMA16816(acc[mi][ni][0], acc[mi][ni][1], acc[mi][ni][2], acc[mi][ni][3],
                             ahi[mi][0], ahi[mi][1], ahi[mi][2], ahi[mi][3],
                             wlo[ni][0], wlo[ni][1]);
                    MMA16816(acc[mi][ni][0], acc[mi][ni][1], acc[mi][ni][2], acc[mi][ni][3],
                             alo[mi][0], alo[mi][1], alo[mi][2], alo[mi][3],
                             whi[ni][0], whi[ni][1]);
                }
            }

            if (pf) {
                cvt_store(alt_hi, alt_lo, (uint32_t)r0 * ROWB + (uint32_t)lid * 8u, nx0);
                cvt_store(alt_hi, alt_lo, (uint32_t)r1 * ROWB + (uint32_t)lid * 8u, nx1);
            }
        }

        __syncthreads();   // A[alt] complete; sh_part free for this iteration

        // ---- epilogue: V-dot partials ----
        const int gid = lid >> 2;
        const int tig = lid & 3;
#pragma unroll
        for (int mi = 0; mi < 2; mi++) {
            float sumA = 0.f, sumB = 0.f;
#pragma unroll
            for (int ni = 0; ni < 8; ni++) {
                int cb = warp_n * 64 + ni * 8 + 2 * tig;
                float v0 = sh_v[cb], v1 = sh_v[cb + 1];
                float q0 = sh_q[cb], q1 = sh_q[cb + 1];
                sumA += v0 * fast_tanh(q0 + acc[mi][ni][0]) + v1 * fast_tanh(q1 + acc[mi][ni][1]);
                sumB += v0 * fast_tanh(q0 + acc[mi][ni][2]) + v1 * fast_tanh(q1 + acc[mi][ni][3]);
            }
            sumA += __shfl_xor_sync(0xffffffff, sumA, 1);
            sumA += __shfl_xor_sync(0xffffffff, sumA, 2);
            sumB += __shfl_xor_sync(0xffffffff, sumB, 1);
            sumB += __shfl_xor_sync(0xffffffff, sumB, 2);
            if (tig == 0) {
                int rowA = warp_m * 32 + mi * 16 + gid;
                sh_part[rowA * 2 + warp_n] = sumA;
                sh_part[(rowA + 8) * 2 + warp_n] = sumB;
            }
        }
        __syncthreads();

        // ---- logits + per-tile softmax partials (deterministic) ----
        float ex = 0.f, mv = -3.0e38f;
        int   mi_ = 0x7fffffff;
        if (tid < TS) {
            float sc = sh_part[tid * 2] + sh_part[tid * 2 + 1] + vb;
            float lg = CLIP_C * fast_tanh(sc)
                     - mask[(size_t)b * SS + s0 + tid] * BIG_NUMBER;
            logits[(size_t)b * SS + s0 + tid] = lg;
            ex = fast_exp(lg - 10.0f);
            mv = lg;
            mi_ = s0 + tid;
        }
#pragma unroll
        for (int off = 16; off; off >>= 1) {
            float oe = __shfl_down_sync(0xffffffff, ex, off);
            float ov = __shfl_down_sync(0xffffffff, mv, off);
            int   oi = __shfl_down_sync(0xffffffff, mi_, off);
            ex += oe;
            if (ov > mv || (ov == mv && oi < mi_)) { mv = ov; mi_ = oi; }
        }
        if (lid == 0) { sh_rs[wid] = ex; sh_rm[wid] = mv; sh_ri[wid] = mi_; }
        __syncthreads();
        if (tid == 0) {
            float s = sh_rs[0], v = sh_rm[0]; int ii = sh_ri[0];
#pragma unroll
            for (int w = 1; w < 8; w++) {
                s += sh_rs[w];
                float wv = sh_rm[w]; int wi = sh_ri[w];
                if (wv > v || (wv == v && wi < ii)) { v = wv; ii = wi; }
            }
            g_psum[t] = s; g_pmaxv[t] = v; g_pmaxi[t] = ii;
        }

        t = tn;
        cur ^= 1;
    }
}

// ---------------------------------------------------------------------------
// Finalize: per batch, reduce 64 tile-partials -> Z, argmax; then one
// streaming pass probs = exp(l-10)/Z; gather + index.
// ---------------------------------------------------------------------------
__global__ void __launch_bounds__(256, 1)
finalize_kernel(const float* __restrict__ logits,
                const float* __restrict__ enc_input,
                float* __restrict__ probs,
                float* __restrict__ out_index,
                float* __restrict__ gathered) {
    const int b = blockIdx.x;
    const int tid = threadIdx.x;
    const int wid = tid >> 5;
    const int lid = tid & 31;

    __shared__ float sh_rs[8], sh_rm[8];
    __shared__ int   sh_ri[8];
    __shared__ float sh_invZ;
    __shared__ int   sh_idx;

    float ps = 0.f, pv = -3.0e38f;
    int   pi = 0x7fffffff;
    if (tid < 64) {
        ps = g_psum[b * 64 + tid];
        pv = g_pmaxv[b * 64 + tid];
        pi = g_pmaxi[b * 64 + tid];
    }
#pragma unroll
    for (int off = 16; off; off >>= 1) {
        float oe = __shfl_down_sync(0xffffffff, ps, off);
        float ov = __shfl_down_sync(0xffffffff, pv, off);
        int   oi = __shfl_down_sync(0xffffffff, pi, off);
        ps += oe;
        if (ov > pv || (ov == pv && oi < pi)) { pv = ov; pi = oi; }
    }
    if (lid == 0) { sh_rs[wid] = ps; sh_rm[wid] = pv; sh_ri[wid] = pi; }
    __syncthreads();
    if (tid == 0) {
        float s = sh_rs[0] + sh_rs[1];
        float v = sh_rm[0]; int ii = sh_ri[0];
        if (sh_rm[1] > v || (sh_rm[1] == v && sh_ri[1] < ii)) { v = sh_rm[1]; ii = sh_ri[1]; }
        sh_invZ = 1.0f / s;
        sh_idx = ii;
    }
    __syncthreads();
    const float invZ = sh_invZ;
    const int idx = sh_idx;

    // streaming probs: 8192 f32 = 2048 float4, 8 per thread
    const float4* L4 = (const float4*)(logits + (size_t)b * SS);
    float4* P4 = (float4*)(probs + (size_t)b * SS);
#pragma unroll
    for (int k = 0; k < 8; k++) {
        int i = tid + 256 * k;
        float4 x = L4[i];
        x.x = fast_exp(x.x - 10.0f) * invZ;
        x.y = fast_exp(x.y - 10.0f) * invZ;
        x.z = fast_exp(x.z - 10.0f) * invZ;
        x.w = fast_exp(x.w - 10.0f) * invZ;
        P4[i] = x;
    }

    if (tid == 0) out_index[b] = (float)idx;
    if (tid < FF)
        gathered[b * FF + tid] = enc_input[((size_t)b * SS + idx) * FF + tid];
}

// ---------------------------------------------------------------------------
// launch
// ---------------------------------------------------------------------------
extern "C" void kernel_launch(void* const* d_in, const int* in_sizes, int n_in,
                              void* d_out, int out_size) {
    const float* dec     = (const float*)d_in[0];
    const float* enc_in  = (const float*)d_in[1];
    const float* enc_out = (const float*)d_in[2];
    const float* mask    = (const float*)d_in[3];
    const float* W1w     = (const float*)d_in[4];
    const float* W1b     = (const float*)d_in[5];
    const float* W2w     = (const float*)d_in[6];
    const float* W2b     = (const float*)d_in[7];
    const float* Vw      = (const float*)d_in[8];
    const float* Vb      = (const float*)d_in[9];

    float* out    = (float*)d_out;
    float* logits = out;
    float* probs  = out + (size_t)BB * SS;
    float* oidx   = out + (size_t)2 * BB * SS;
    float* gath   = oidx + BB;

    cudaFuncSetAttribute(prep_kernel,
                         cudaFuncAttributeMaxDynamicSharedMemorySize, DD * UU * 4);
    cudaFuncSetAttribute(main_kernel,
                         cudaFuncAttributeMaxDynamicSharedMemorySize, SM_TOTAL);

    prep_kernel<<<BB + 16, 256, DD * UU * 4>>>(dec, W1w, W1b, W2b, W2w);
    main_kernel<<<GRID_MAIN, 256, SM_TOTAL>>>(enc_out, mask, Vw, Vb, logits);
    finalize_kernel<<<BB, 256>>>(logits, enc_in, probs, oidx, gath);
}

// round 16
// speedup vs baseline: 1.0160x; 1.0160x over previous
#include <cuda_runtime.h>
#include <cuda_bf16.h>
#include <cstdint>

// ---------------------------------------------------------------------------
// Problem constants
// ---------------------------------------------------------------------------
#define BB 64
#define SS 8192
#define DD 128
#define UU 128
#define FF 16
#define CLIP_C 10.0f
#define BIG_NUMBER 1e9f
#define TS 128
#define NTILES 4096          // (SS/TS) * BB ; tile t: b = t>>6, s0 = (t&63)*TS
#define GRID_MAIN 152        // GB300 SM count

// Scratch (device globals; no allocation allowed)
__device__ float g_qb[BB * UU];

// ---------------------------------------------------------------------------
// Helpers (baseline PTX only)
// ---------------------------------------------------------------------------
__device__ __forceinline__ uint32_t smem_u32(const void* p) {
    uint32_t a;
    asm("{ .reg .u64 t; cvta.to.shared.u64 t, %1; cvt.u32.u64 %0, t; }"
        : "=r"(a) : "l"(p));
    return a;
}

#define LDMX4(r0, r1, r2, r3, addr) \
    asm volatile("ldmatrix.sync.aligned.m8n8.x4.shared.b16 {%0,%1,%2,%3}, [%4];" \
                 : "=r"(r0), "=r"(r1), "=r"(r2), "=r"(r3) : "r"(addr))

#define MMA16816(c0, c1, c2, c3, a0, a1, a2, a3, b0, b1) \
    asm volatile("mma.sync.aligned.m16n8k16.row.col.f32.bf16.bf16.f32 " \
                 "{%0,%1,%2,%3}, {%4,%5,%6,%7}, {%8,%9}, {%0,%1,%2,%3};" \
                 : "+f"(c0), "+f"(c1), "+f"(c2), "+f"(c3) \
                 : "r"(a0), "r"(a1), "r"(a2), "r"(a3), "r"(b0), "r"(b1))

__device__ __forceinline__ float fast_tanh(float x) {
    float e, r;
    asm("ex2.approx.f32 %0, %1;" : "=f"(e) : "f"(x * 2.885390081777927f));
    asm("rcp.approx.f32 %0, %1;" : "=f"(r) : "f"(e + 1.0f));
    return fmaf(-2.0f, r, 1.0f);
}

__device__ __forceinline__ float fast_exp(float x) {
    float e;
    asm("ex2.approx.f32 %0, %1;" : "=f"(e) : "f"(x * 1.4426950408889634f));
    return e;
}

// convert one fp32 float4 -> bf16 hi/lo packed pairs, store to A buffers
__device__ __forceinline__ void cvt_store(unsigned char* base_hi,
                                          unsigned char* base_lo,
                                          uint32_t off, float4 x) {
    __nv_bfloat16 h0 = __float2bfloat16(x.x), h1 = __float2bfloat16(x.y);
    __nv_bfloat16 h2 = __float2bfloat16(x.z), h3 = __float2bfloat16(x.w);
    __nv_bfloat162 hp0 = __halves2bfloat162(h0, h1);
    __nv_bfloat162 hp1 = __halves2bfloat162(h2, h3);
    __nv_bfloat162 lp0 = __halves2bfloat162(
        __float2bfloat16(x.x - __bfloat162float(h0)),
        __float2bfloat16(x.y - __bfloat162float(h1)));
    __nv_bfloat162 lp1 = __halves2bfloat162(
        __float2bfloat16(x.z - __bfloat162float(h2)),
        __float2bfloat16(x.w - __bfloat162float(h3)));
    *(uint2*)(base_hi + off) = make_uint2(*(uint32_t*)&hp0, *(uint32_t*)&hp1);
    *(uint2*)(base_lo + off) = make_uint2(*(uint32_t*)&lp0, *(uint32_t*)&lp1);
}

// ---------------------------------------------------------------------------
// Prep: qb only (one block per batch, W1 cached in smem)
// ---------------------------------------------------------------------------
extern __shared__ float prep_sm[];

__global__ void prep_kernel(const float* __restrict__ dec,
                            const float* __restrict__ W1w,
                            const float* __restrict__ W1b,
                            const float* __restrict__ W2b) {
    int blk = blockIdx.x;
    int tid = threadIdx.x;
    __shared__ float dsh[DD];
    if (tid < DD) dsh[tid] = dec[blk * DD + tid];
    for (int i = tid; i < (DD * UU) / 4; i += 256)
        ((float4*)prep_sm)[i] = ((const float4*)W1w)[i];
    __syncthreads();
    if (tid < UU) {
        float acc = 0.f;
#pragma unroll 8
        for (int d = 0; d < DD; d++) acc += dsh[d] * prep_sm[d * UU + tid];
        g_qb[blk * UU + tid] = acc + W1b[tid] + W2b[tid];
    }
}

// ---------------------------------------------------------------------------
// Main: persistent CTAs, static schedule. W2 split converted from global
// ONCE per CTA (no intermediate global). Double-buffered A with interleaved
// LDG+convert inside the MMA kk-loop. Fast-tanh epilogue.
// ---------------------------------------------------------------------------
#define ROWB 272u
#define SM_W_HI  0u
#define SM_W_LO  (SM_W_HI + 128u * ROWB)     // 34816
#define SM_A0    (SM_W_LO + 128u * ROWB)     // 69632  (hi at +0, lo at +34816)
#define SM_A1    (SM_A0 + 2u * 128u * ROWB)  // 139264
#define SM_AUX   (SM_A1 + 2u * 128u * ROWB)  // 208896
#define SM_Q0    (SM_AUX)                    // 128 f32
#define SM_Q1    (SM_AUX + 512u)             // 128 f32
#define SM_V     (SM_AUX + 1024u)            // 128 f32
#define SM_PART  (SM_AUX + 1536u)            // 128*2 f32
#define SM_TOTAL (SM_AUX + 2560u)            // 211456

extern __shared__ unsigned char smx[];

__global__ void __launch_bounds__(256, 1)
main_kernel(const float* __restrict__ enc_out,
            const float* __restrict__ mask,
            const float* __restrict__ W2w,
            const float* __restrict__ Vw,
            const float* __restrict__ Vb,
            float* __restrict__ logits) {
    const int bid = blockIdx.x;
    const int tid = threadIdx.x;
    const int wid = tid >> 5;
    const int lid = tid & 31;
    const int warp_m = wid & 3;
    const int warp_n = wid >> 2;
    const uint32_t sb = smem_u32(smx);

    float* sh_v    = (float*)(smx + SM_V);
    float* sh_part = (float*)(smx + SM_PART);

    const float vb = Vb[0];
    if (tid < UU) sh_v[tid] = Vw[tid];

    // ---- W2 split: convert from global ONCE per CTA (coalesced over u) ----
    {
        const int u    = tid & 127;
        const int half = tid >> 7;          // d-range half
        unsigned char* whi = smx + SM_W_HI + (uint32_t)u * ROWB;
        unsigned char* wlo = smx + SM_W_LO + (uint32_t)u * ROWB;
#pragma unroll 8
        for (int dd = 0; dd < 64; dd++) {
            int d = half * 64 + dd;
            float x = W2w[d * UU + u];
            __nv_bfloat16 h = __float2bfloat16(x);
            float lo = x - __bfloat162float(h);
            *(__nv_bfloat16*)(whi + d * 2) = h;
            *(__nv_bfloat16*)(wlo + d * 2) = __float2bfloat16(lo);
        }
    }

    // ---- initial convert of tile t into A0 (latency exposed once) ----
    int t = bid;
    if (t < NTILES) {
        const int b  = t >> 6;
        const int s0 = (t & 63) * TS;
        const float* src = enc_out + ((size_t)b * SS + s0) * DD;
        unsigned char* bhi = smx + SM_A0;
        unsigned char* blo = smx + SM_A0 + 34816u;
#pragma unroll
        for (int i = 0; i < 16; i++) {
            int r = wid + 8 * i;
            float4 x = *(const float4*)(src + (size_t)r * DD + lid * 4);
            cvt_store(bhi, blo, (uint32_t)r * ROWB + (uint32_t)lid * 8u, x);
        }
        if (tid < UU) ((float*)(smx + SM_Q0))[tid] = g_qb[b * UU + tid];
    }
    __syncthreads();

    // ---- per-lane ldmatrix base offsets (relative) ----
    const uint32_t a_off = (uint32_t)(lid & 15) * ROWB + (uint32_t)((lid >> 4) & 1) * 16u
                           + (uint32_t)(warp_m * 32) * ROWB;
    const uint32_t b_off = ((uint32_t)(lid & 7) + (uint32_t)((lid >> 4) & 1) * 8u) * ROWB
                           + (uint32_t)((lid >> 3) & 1) * 16u
                           + (uint32_t)(warp_n * 64) * ROWB;
    const uint32_t w_hi_base = sb + SM_W_HI + b_off;
    const uint32_t w_lo_base = sb + SM_W_LO + b_off;

    int cur = 0;
    while (t < NTILES) {
        const int b  = t >> 6;
        const int s0 = (t & 63) * TS;
        const int tn = t + GRID_MAIN;
        const bool pf = tn < NTILES;

        const uint32_t a_cur = cur ? SM_A1 : SM_A0;
        const uint32_t a_alt = cur ? SM_A0 : SM_A1;
        const uint32_t a_hi_base = sb + a_cur + a_off;
        const uint32_t a_lo_base = sb + a_cur + 34816u + a_off;
        unsigned char* alt_hi = smx + a_alt;
        unsigned char* alt_lo = smx + a_alt + 34816u;
        float* sh_q  = (float*)(smx + (cur ? SM_Q1 : SM_Q0));
        float* sh_qn = (float*)(smx + (cur ? SM_Q0 : SM_Q1));

        const float* nsrc = nullptr;
        if (pf) {
            const int bn  = tn >> 6;
            const int sn0 = (tn & 63) * TS;
            nsrc = enc_out + ((size_t)bn * SS + sn0) * DD;
            if (tid < UU) sh_qn[tid] = g_qb[bn * UU + tid];
        }

        // ---- fused 3-term MMA mainloop + interleaved next-tile convert ----
        float acc[2][8][4];
#pragma unroll
        for (int mi = 0; mi < 2; mi++)
#pragma unroll
            for (int ni = 0; ni < 8; ni++)
#pragma unroll
                for (int j = 0; j < 4; j++) acc[mi][ni][j] = 0.f;

#pragma unroll 1
        for (int kk = 0; kk < 8; kk++) {
            const uint32_t kb = (uint32_t)kk * 32u;

            float4 nx0, nx1;
            int r0 = wid + 8 * (2 * kk);
            int r1 = wid + 8 * (2 * kk + 1);
            if (pf) {
                nx0 = *(const float4*)(nsrc + (size_t)r0 * DD + lid * 4);
                nx1 = *(const float4*)(nsrc + (size_t)r1 * DD + lid * 4);
            }

            uint32_t ahi[2][4], alo[2][4];
            LDMX4(ahi[0][0], ahi[0][1], ahi[0][2], ahi[0][3], a_hi_base + kb);
            LDMX4(ahi[1][0], ahi[1][1], ahi[1][2], ahi[1][3], a_hi_base + 16u * ROWB + kb);
            LDMX4(alo[0][0], alo[0][1], alo[0][2], alo[0][3], a_lo_base + kb);
            LDMX4(alo[1][0], alo[1][1], alo[1][2], alo[1][3], a_lo_base + 16u * ROWB + kb);
            uint32_t whi[8][2], wlo[8][2];
#pragma unroll
            for (int np = 0; np < 4; np++) {
                LDMX4(whi[2 * np][0], whi[2 * np][1], whi[2 * np + 1][0], whi[2 * np + 1][1],
                      w_hi_base + (uint32_t)(np * 16) * ROWB + kb);
                LDMX4(wlo[2 * np][0], wlo[2 * np][1], wlo[2 * np + 1][0], wlo[2 * np + 1][1],
                      w_lo_base + (uint32_t)(np * 16) * ROWB + kb);
            }
#pragma unroll
            for (int mi = 0; mi < 2; mi++) {
#pragma unroll
                for (int ni = 0; ni < 8; ni++) {
                    MMA16816(acc[mi][ni][0], acc[mi][ni][1], acc[mi][ni][2], acc[mi][ni][3],
                             ahi[mi][0], ahi[mi][1], ahi[mi][2], ahi[mi][3],
                             whi[ni][0], whi[ni][1]);
                    MMA16816(acc[mi][ni][0], acc[mi][ni][1], acc[mi][ni][2], acc[mi][ni][3],
                             ahi[mi][0], ahi[mi][1], ahi[mi][2], ahi[mi][3],
                             wlo[ni][0], wlo[ni][1]);
                    MMA16816(acc[mi][ni][0], acc[mi][ni][1], acc[mi][ni][2], acc[mi][ni][3],
                             alo[mi][0], alo[mi][1], alo[mi][2], alo[mi][3],
                             whi[ni][0], whi[ni][1]);
                }
            }

            if (pf) {
                cvt_store(alt_hi, alt_lo, (uint32_t)r0 * ROWB + (uint32_t)lid * 8u, nx0);
                cvt_store(alt_hi, alt_lo, (uint32_t)r1 * ROWB + (uint32_t)lid * 8u, nx1);
            }
        }

        __syncthreads();   // A[alt] complete; sh_part free for this iteration

        // ---- epilogue ----
        const int gid = lid >> 2;
        const int tig = lid & 3;
#pragma unroll
        for (int mi = 0; mi < 2; mi++) {
            float sumA = 0.f, sumB = 0.f;
#pragma unroll
            for (int ni = 0; ni < 8; ni++) {
                int cb = warp_n * 64 + ni * 8 + 2 * tig;
                float v0 = sh_v[cb], v1 = sh_v[cb + 1];
                float q0 = sh_q[cb], q1 = sh_q[cb + 1];
                sumA += v0 * fast_tanh(q0 + acc[mi][ni][0]) + v1 * fast_tanh(q1 + acc[mi][ni][1]);
                sumB += v0 * fast_tanh(q0 + acc[mi][ni][2]) + v1 * fast_tanh(q1 + acc[mi][ni][3]);
            }
            sumA += __shfl_xor_sync(0xffffffff, sumA, 1);
            sumA += __shfl_xor_sync(0xffffffff, sumA, 2);
            sumB += __shfl_xor_sync(0xffffffff, sumB, 1);
            sumB += __shfl_xor_sync(0xffffffff, sumB, 2);
            if (tig == 0) {
                int rowA = warp_m * 32 + mi * 16 + gid;
                sh_part[rowA * 2 + warp_n] = sumA;
                sh_part[(rowA + 8) * 2 + warp_n] = sumB;
            }
        }
        __syncthreads();
        if (tid < TS) {
            float sc = sh_part[tid * 2] + sh_part[tid * 2 + 1] + vb;
            float lg = CLIP_C * fast_tanh(sc)
                     - mask[(size_t)b * SS + s0 + tid] * BIG_NUMBER;
            logits[(size_t)b * SS + s0 + tid] = lg;
        }

        t = tn;
        cur ^= 1;
    }
}

// ---------------------------------------------------------------------------
// Softmax + first-occurrence argmax + gather (per batch), single-pass
// ---------------------------------------------------------------------------
#define SM_THREADS 512
#define PER_TH (SS / SM_THREADS)   // 16

__global__ void softmax_kernel(const float* __restrict__ logits,
                               const float* __restrict__ enc_input,
                               float* __restrict__ probs,
                               float* __restrict__ out_index,
                               float* __restrict__ gathered) {
    const int b = blockIdx.x;
    const int tid = threadIdx.x;
    const float* L = logits + (size_t)b * SS;
    float* P = probs + (size_t)b * SS;

    __shared__ float smax[SM_THREADS];
    __shared__ int   sidx[SM_THREADS];
    __shared__ float ssum[SM_THREADS];

    float vals[PER_TH];
    float bm = -3.0e38f; int bi = 0;
#pragma unroll
    for (int k = 0; k < PER_TH; k++) {
        int s = tid + k * SM_THREADS;
        float v = L[s];
        vals[k] = v;
        if (v > bm) { bm = v; bi = s; }
    }
    smax[tid] = bm; sidx[tid] = bi;
    __syncthreads();
    for (int off = SM_THREADS / 2; off > 0; off >>= 1) {
        if (tid < off) {
            float ov = smax[tid + off]; int oi = sidx[tid + off];
            if (ov > smax[tid] || (ov == smax[tid] && oi < sidx[tid])) {
                smax[tid] = ov; sidx[tid] = oi;
            }
        }
        __syncthreads();
    }
    const float M = smax[0];
    const int idx = sidx[0];

    float ls = 0.f;
#pragma unroll
    for (int k = 0; k < PER_TH; k++) {
        vals[k] = fast_exp(vals[k] - M);
        ls += vals[k];
    }
    ssum[tid] = ls;
    __syncthreads();
    for (int off = SM_THREADS / 2; off > 0; off >>= 1) {
        if (tid < off) ssum[tid] += ssum[tid + off];
        __syncthreads();
    }
    const float invZ = 1.0f / ssum[0];

#pragma unroll
    for (int k = 0; k < PER_TH; k++)
        P[tid + k * SM_THREADS] = vals[k] * invZ;

    if (tid == 0) out_index[b] = (float)idx;
    if (tid < FF)
        gathered[b * FF + tid] = enc_input[((size_t)b * SS + idx) * FF + tid];
}

// ---------------------------------------------------------------------------
// launch
// ---------------------------------------------------------------------------
extern "C" void kernel_launch(void* const* d_in, const int* in_sizes, int n_in,
                              void* d_out, int out_size) {
    const float* dec     = (const float*)d_in[0];
    const float* enc_in  = (const float*)d_in[1];
    const float* enc_out = (const float*)d_in[2];
    const float* mask    = (const float*)d_in[3];
    const float* W1w     = (const float*)d_in[4];
    const float* W1b     = (const float*)d_in[5];
    const float* W2w     = (const float*)d_in[6];
    const float* W2b     = (const float*)d_in[7];
    const float* Vw      = (const float*)d_in[8];
    const float* Vb      = (const float*)d_in[9];

    float* out    = (float*)d_out;
    float* logits = out;
    float* probs  = out + (size_t)BB * SS;
    float* oidx   = out + (size_t)2 * BB * SS;
    float* gath   = oidx + BB;

    cudaFuncSetAttribute(prep_kernel,
                         cudaFuncAttributeMaxDynamicSharedMemorySize, DD * UU * 4);
    cudaFuncSetAttribute(main_kernel,
                         cudaFuncAttributeMaxDynamicSharedMemorySize, SM_TOTAL);

    prep_kernel<<<BB, 256, DD * UU * 4>>>(dec, W1w, W1b, W2b);
    main_kernel<<<GRID_MAIN, 256, SM_TOTAL>>>(enc_out, mask, W2w, Vw, Vb, logits);
    softmax_kernel<<<BB, SM_THREADS>>>(logits, enc_in, probs, oidx, gath);
}